// round 1
// baseline (speedup 1.0000x reference)
#include <cuda_runtime.h>
#include <stdint.h>

// Scratch: winner[s] = largest sample index p that writes slot s, or -1.
// N = 16384 is fixed by the problem shape (buffer is 16384 x 256).
#define N_SLOTS 16384
#define D_DIM   256

__device__ int g_winner[N_SLOTS];

// K0: reset winner array every launch (deterministic across graph replays).
__global__ void rs_init_kernel() {
    int s = blockIdx.x * blockDim.x + threadIdx.x;
    if (s < N_SLOTS) g_winner[s] = -1;
}

// K1: each sample p computes its target slot and atomicMax's its index in.
__global__ void rs_scatter_kernel(const float* __restrict__ u,
                                  const int* __restrict__ i0_ptr,
                                  int b, int n) {
    int p = blockIdx.x * blockDim.x + threadIdx.x;
    if (p >= b) return;
    int i0 = *i0_ptr;
    int pos = i0 + p;
    int idx;
    if (pos < n) {
        idx = pos;                       // deterministic fill phase
    } else {
        // match JAX exactly: floor(u * float(pos+1)) in f32, then clamp to pos
        float prod = u[p] * (float)(pos + 1);
        int r = (int)floorf(prod);
        idx = r < pos ? r : pos;
    }
    if (idx < n) {
        atomicMax(&g_winner[idx], p);
    }
}

// K2: gather winning rows (or keep old buffer row) into the output.
// One float4 per thread: 64 threads per row of D=256.
__global__ void rs_gather_kernel(const float4* __restrict__ samples,
                                 const float4* __restrict__ buffer,
                                 float4* __restrict__ out,
                                 int n) {
    int t = blockIdx.x * blockDim.x + threadIdx.x;
    int total = n * (D_DIM / 4);
    if (t >= total) return;
    int s  = t >> 6;          // t / 64
    int d4 = t & 63;          // t % 64
    int w = g_winner[s];
    const float4* src = (w >= 0) ? (samples + (size_t)w * (D_DIM / 4))
                                 : (buffer  + (size_t)s * (D_DIM / 4));
    out[t] = src[d4];
}

extern "C" void kernel_launch(void* const* d_in, const int* in_sizes, int n_in,
                              void* d_out, int out_size) {
    const float* samples = (const float*)d_in[0];   // [B, 256]
    const float* buffer  = (const float*)d_in[1];   // [N, 256]
    const float* u       = (const float*)d_in[2];   // [B]
    const int*   i0      = (const int*)d_in[3];     // scalar

    int b = in_sizes[2];                // B from u's element count
    int n = in_sizes[1] / D_DIM;        // N from buffer element count

    // K0: init winners
    rs_init_kernel<<<(N_SLOTS + 255) / 256, 256>>>();

    // K1: scatter sample indices with atomicMax
    rs_scatter_kernel<<<(b + 255) / 256, 256>>>(u, i0, b, n);

    // K2: gather rows into output
    int total4 = n * (D_DIM / 4);
    rs_gather_kernel<<<(total4 + 255) / 256, 256>>>(
        (const float4*)samples, (const float4*)buffer, (float4*)d_out, n);
}